// round 13
// baseline (speedup 1.0000x reference)
#include <cuda_runtime.h>

typedef unsigned int uint;

__device__ __forceinline__ float tanhx(float x) {
    float y; asm("tanh.approx.f32 %0, %1;" : "=f"(y) : "f"(x)); return y;
}
__device__ __forceinline__ uint cvt_tf32(float x) {
    uint r; asm("cvt.rna.tf32.f32 %0, %1;" : "=r"(r) : "f"(x)); return r;
}
// Dice via tanh: dice(x) = x * fma(C2, tanh(fma(x, S2, MS2)), A2)
__device__ __forceinline__ float dice4(float x, float4 c) {
    return x * fmaf(c.y, tanhx(fmaf(x, c.z, c.w)), c.x);
}
// m16n8k8 tf32 warp MMA (A row-major, B col-major, fp32 accum)
__device__ __forceinline__ void mma16n8k8(float& d0, float& d1, float& d2, float& d3,
                                          uint a0, uint a1, uint a2, uint a3,
                                          uint b0, uint b1) {
    asm("mma.sync.aligned.m16n8k8.row.col.f32.tf32.tf32.f32 "
        "{%0,%1,%2,%3}, {%4,%5,%6,%7}, {%8,%9}, {%0,%1,%2,%3};"
        : "+f"(d0), "+f"(d1), "+f"(d2), "+f"(d3)
        : "r"(a0), "r"(a1), "r"(a2), "r"(a3), "r"(b0), "r"(b1));
}
// slot interleave within each 8-index block: (8m+g, 8m+g+4) -> (8m+2g, 8m+2g+1)
__device__ __forceinline__ int slot_of(int c) {
    return (c & ~7) + 2 * (c & 3) + ((c >> 2) & 1);
}
// inverse of slot_of within each 8-block
__device__ __forceinline__ int unslot(int s) {
    return (s & ~7) + ((s & 7) >> 1) + 4 * (s & 1);
}

static constexpr int NT   = 416;     // 13 warps = 13 tiles
static constexpr int MROW = 24;      // Mtc stride

// ---- batch-independent precomputed images (written by setup_kernel) ----
// W1 B-fragments, read directly via LDG (L1-resident, ~15 KB total):
//  g_W1p[j5p*320 + kt*32 + rw*4 + g] = { B0(2*j5p), B1(2*j5p), B0(2*j5p+1), B1(2*j5p+1) }
//  g_W1s[kt*32 + rw*4 + g]           = { B0(4), B1(4) }
//  where B0(j5)=tf32(W1[8kt+g][8*j5+rw]), B1(j5)=tf32(W1[8kt+g+4][8*j5+rw])
__device__ float4 g_W1p[640];
__device__ float2 g_W1s[320];
__device__ float  g_Wk [80 * MROW];  // Mtc-layout image of W0[12+k][o]-W0[24+k][o]
__device__ float  g_Wq [80 * MROW];  // Mtc-layout image of W0[36+k][o]
__device__ float  g_Wbt[80 * 12];    // Wbt[o*12+i] = W0[i][o] + W0[24+i][o]
__device__ float4 g_cst[130];        // [0..79]=d0c, [80..119]=d1c, [120..129]=b1

__global__ void setup_kernel(
    const float* __restrict__ W0, const float* __restrict__ W1,
    const float* __restrict__ b1,
    const float* __restrict__ alpha0, const float* __restrict__ alpha1,
    const float* __restrict__ mm0, const float* __restrict__ mv0,
    const float* __restrict__ mm1, const float* __restrict__ mv1,
    const float* __restrict__ ak)
{
    const int tid = threadIdx.x;
    const float EPS = 1e-9f;
    // W1 fragment images
    for (int idx = tid; idx < 640; idx += 256) {
        int j5p = idx / 320, r = idx % 320;
        int kt = r / 32, rw = (r % 32) / 4, g = r % 4;
        int row0 = (8 * kt + g) * 40, row1 = (8 * kt + g + 4) * 40;
        int jc = 16 * j5p + rw;
        float4 v;
        v.x = __uint_as_float(cvt_tf32(W1[row0 + jc]));
        v.y = __uint_as_float(cvt_tf32(W1[row1 + jc]));
        v.z = __uint_as_float(cvt_tf32(W1[row0 + jc + 8]));
        v.w = __uint_as_float(cvt_tf32(W1[row1 + jc + 8]));
        g_W1p[idx] = v;
    }
    for (int idx = tid; idx < 320; idx += 256) {
        int kt = idx / 32, rw = (idx % 32) / 4, g = idx % 4;
        int jc = 32 + rw;
        float2 v;
        v.x = __uint_as_float(cvt_tf32(W1[(8 * kt + g) * 40 + jc]));
        v.y = __uint_as_float(cvt_tf32(W1[(8 * kt + g + 4) * 40 + jc]));
        g_W1s[idx] = v;
    }
    // Wk/Wq images in final Mtc layout: phys row po=slot(o), col s=slot(k); k>=12 -> 0
    for (int idx = tid; idx < 80 * MROW; idx += 256) {
        int po = idx / MROW, s = idx % MROW;
        int o = unslot(po);
        float wk = 0.0f, wq = 0.0f;
        if (s < 16) {
            int k = unslot(s);
            if (k < 12) {
                wk = W0[(12 + k) * 80 + o] - W0[(24 + k) * 80 + o];
                wq = W0[(36 + k) * 80 + o];
            }
        }
        g_Wk[idx] = wk;
        g_Wq[idx] = wq;
    }
    // Wbt transposed: Wbt[o*12+i] = W0[i][o] + W0[24+i][o]
    for (int idx = tid; idx < 960; idx += 256) {
        int o = idx / 12, i = idx % 12;
        g_Wbt[idx] = W0[i * 80 + o] + W0[(24 + i) * 80 + o];
    }
    // dice constants
    if (tid < 80) {
        float a  = alpha0[tid];
        float c2 = 0.5f * (1.0f - a);
        float s2 = 0.5f * rsqrtf(mv0[tid] + EPS);
        g_cst[tid] = make_float4(a + c2, c2, s2, -mm0[tid] * s2);
    }
    if (tid >= 128 && tid < 168) {
        int o = tid - 128;
        float a  = alpha1[o];
        float kk = ak[o];
        float c2 = 0.5f * (1.0f - a);
        float s2 = 0.5f * rsqrtf(mv1[o] + EPS);
        // h includes b1 (folded into hc accumulator init)
        g_cst[80 + o] = make_float4((a + c2) * kk, c2 * kk, s2, -mm1[o] * s2);
    }
    if (tid >= 192 && tid < 202) {
        int p = tid - 192;
        g_cst[120 + p] = make_float4(b1[4*p], b1[4*p+1], b1[4*p+2], b1[4*p+3]);
    }
}

// Shared layout (floats):
static constexpr int O_KSH   = 0;                     // ksh [208][12]    2496
static constexpr int O_MTC   = 2496;                  // Mtc [80][24]     1920
static constexpr int O_CST   = O_MTC + 80*MROW;       // d0c|d1c|b1d      520
static constexpr int O_BASE  = O_CST + 520;           // base [80]        80
static constexpr int O_SC    = O_BASE + 80;           // sc [208]         208
static constexpr int O_PSUM  = O_SC + 208;            // psum [192]       192
static constexpr int O_QS    = O_PSUM + 192;          // qs [12]          12
static constexpr int O_QSLOT = O_QS + 12;             // qslot [24]       24
static constexpr int O_SC0   = O_QSLOT + 24;          // score0 (+pad)    4
static constexpr int SMEM_FLOATS = O_SC0 + 4;         // 5460
static constexpr int SMEM_BYTES  = SMEM_FLOATS * 4;   // 21840 B -> 3 CTAs/SM

__global__ void __launch_bounds__(NT, 3) din_kernel(
    const float* __restrict__ query, const float* __restrict__ keys,
    const float* __restrict__ b0, const float* __restrict__ ab,
    float* __restrict__ out)
{
    extern __shared__ __align__(16) float smf[];
    float*  ksh   = smf + O_KSH;     // keys natural [208][12], rows 200-207 zero
    float*  Mtc   = smf + O_MTC;
    float4* d0c   = (float4*)(smf + O_CST);
    float4* d1c   = (float4*)(smf + O_CST + 320);
    float*  b1d   = smf + O_CST + 480;
    float*  basef = smf + O_BASE;
    float*  sc    = smf + O_SC;
    float*  psum  = smf + O_PSUM;
    float*  qs    = smf + O_QS;
    float*  qslot = smf + O_QSLOT;

    const int tid  = threadIdx.x;
    const int b    = blockIdx.x;
    const int wid  = tid >> 5;
    const int lane = tid & 31;
    const int g    = lane & 3;    // k/n group
    const int rw   = lane >> 2;   // row within fragment

    if (tid < 12) qs[tid] = query[b * 12 + tid];
    if (tid == 0) smf[O_SC0] = ab[0];
    __syncthreads();  // qs ready

    // ============ Phase A stage 1: copies + base + qslot ============
    {
        const float4* gk = (const float4*)(keys + (size_t)b * 2400);
        float4* sk = (float4*)ksh;
        for (int i = tid; i < 600; i += NT) sk[i] = gk[i];
        if (tid < 96) ksh[2400 + tid] = 0.0f;
    }
    if (tid < 130) ((float4*)(smf + O_CST))[tid] = g_cst[tid];
    if (tid < 24) {
        float v = 0.0f;
        if (tid < 16) { int k = unslot(tid); if (k < 12) v = qs[k]; }
        qslot[tid] = v;
    }
    if (tid < 80) {
        float s = b0[tid];
        const float4* wb = (const float4*)(g_Wbt + tid * 12);
        float4 w0v = wb[0], w1v = wb[1], w2v = wb[2];
        s += qs[0]*w0v.x + qs[1]*w0v.y + qs[2]*w0v.z  + qs[3]*w0v.w
           + qs[4]*w1v.x + qs[5]*w1v.y + qs[6]*w1v.z  + qs[7]*w1v.w
           + qs[8]*w2v.x + qs[9]*w2v.y + qs[10]*w2v.z + qs[11]*w2v.w;
        basef[tid] = s;
    }
    __syncthreads();

    // ============ Phase A stage 2: Mtc = cvt_tf32(Wk + q*Wq); slot 9 = base ====
    for (int i = tid; i < 480; i += NT) {
        float4 wk = ((const float4*)g_Wk)[i];
        float4 wq = ((const float4*)g_Wq)[i];
        float4 q4 = ((const float4*)qslot)[i % 6];
        float4 v;
        v.x = __uint_as_float(cvt_tf32(fmaf(q4.x, wq.x, wk.x)));
        v.y = __uint_as_float(cvt_tf32(fmaf(q4.y, wq.y, wk.y)));
        v.z = __uint_as_float(cvt_tf32(fmaf(q4.z, wq.z, wk.z)));
        v.w = __uint_as_float(cvt_tf32(fmaf(q4.w, wq.w, wk.w)));
        // float4 i%6==2 covers slots 8..11 of row i/6; slot 9 = bias row (k=12)
        if (i % 6 == 2) v.y = __uint_as_float(cvt_tf32(basef[unslot(i / 6)]));
        ((float4*)Mtc)[i] = v;
    }
    __syncthreads();

    // ===== Fused tile (1 per warp): per jt: layer0 HMMA -> dice0 -> layer1 HMMA =
    {
        const float score0 = smf[O_SC0];
        const int pt = wid;                       // 13 warps, 13 tiles
        const int r0 = pt * 16 + rw, r1 = r0 + 8;

        // k-fragments, RNA tf32 rounding
        const float* k0p = ksh + r0 * 12;
        const float* k1p = ksh + r1 * 12;
        uint ka0 = cvt_tf32(k0p[g]),     ka1 = cvt_tf32(k1p[g]);
        uint ka2 = cvt_tf32(k0p[g + 4]), ka3 = cvt_tf32(k1p[g + 4]);
        uint kb0 = cvt_tf32(k0p[8 + g]), kb1 = cvt_tf32(k1p[8 + g]);
        uint one = (g == 0) ? 0x3F800000u : 0u;   // logical k=12 = bias column

        // layer-1 accumulators, b1 folded into init
        float hc[5][4];
        #pragma unroll
        for (int j5 = 0; j5 < 5; ++j5) {
            float2 bb = *(const float2*)(b1d + j5 * 8 + 2 * g);
            hc[j5][0] = bb.x; hc[j5][1] = bb.y;
            hc[j5][2] = bb.x; hc[j5][3] = bb.y;
        }

        // W1 fragment pointers (global, L1-resident)
        const float4* w1p0 = g_W1p + (rw * 4 + g);
        const float4* w1p1 = w1p0 + 320;
        const float2* w1s  = g_W1s + (rw * 4 + g);

        #pragma unroll
        for (int jt = 0; jt < 10; ++jt) {
            // ---- layer 0 for channels 8jt+{g,g+4}; bias via ones-column ----
            float acc0 = 0.f, acc1 = 0.f, acc2 = 0.f, acc3 = 0.f;
            const float* mrow = Mtc + (jt * 8 + rw) * MROW + 2 * g;
            float2 w0 = *(const float2*)(mrow);       // logical k: g, g+4
            float2 w1 = *(const float2*)(mrow + 8);   // logical k: 8+g, 12+g(bias)
            mma16n8k8(acc0, acc1, acc2, acc3, ka0, ka1, ka2, ka3,
                      __float_as_uint(w0.x), __float_as_uint(w0.y));
            mma16n8k8(acc0, acc1, acc2, acc3, kb0, kb1, one, one,
                      __float_as_uint(w1.x), __float_as_uint(w1.y));
            // ---- dice0 in-register, RNA tf32 ----
            float4 ca = d0c[8 * jt + g];
            float4 cb = d0c[8 * jt + g + 4];
            uint af0 = cvt_tf32(dice4(acc0, ca));  // D[rw][8jt+g]
            uint af1 = cvt_tf32(dice4(acc2, ca));  // D[rw+8][8jt+g]
            uint af2 = cvt_tf32(dice4(acc1, cb));  // D[rw][8jt+g+4]
            uint af3 = cvt_tf32(dice4(acc3, cb));  // D[rw+8][8jt+g+4]
            // ---- layer 1 partial: jt is layer-1's k-tile; W1 frags via LDG ----
            float4 wA = w1p0[jt * 32];   // j5 = 0,1
            float4 wB = w1p1[jt * 32];   // j5 = 2,3
            float2 wC = w1s [jt * 32];   // j5 = 4
            mma16n8k8(hc[0][0], hc[0][1], hc[0][2], hc[0][3], af0, af1, af2, af3,
                      __float_as_uint(wA.x), __float_as_uint(wA.y));
            mma16n8k8(hc[1][0], hc[1][1], hc[1][2], hc[1][3], af0, af1, af2, af3,
                      __float_as_uint(wA.z), __float_as_uint(wA.w));
            mma16n8k8(hc[2][0], hc[2][1], hc[2][2], hc[2][3], af0, af1, af2, af3,
                      __float_as_uint(wB.x), __float_as_uint(wB.y));
            mma16n8k8(hc[3][0], hc[3][1], hc[3][2], hc[3][3], af0, af1, af2, af3,
                      __float_as_uint(wB.z), __float_as_uint(wB.w));
            mma16n8k8(hc[4][0], hc[4][1], hc[4][2], hc[4][3], af0, af1, af2, af3,
                      __float_as_uint(wC.x), __float_as_uint(wC.y));
        }

        // ---- epilogue: dice1(+ak folded; h includes b1), row sums, reduce ----
        float s0 = 0.0f, s1 = 0.0f;
        #pragma unroll
        for (int j5 = 0; j5 < 5; ++j5) {
            const int ja = j5 * 8 + 2 * g;
            float4 ca = d1c[ja], cb = d1c[ja + 1];
            float c0 = hc[j5][0], c1 = hc[j5][1];
            float c2 = hc[j5][2], c3 = hc[j5][3];
            s0 = fmaf(c0, fmaf(ca.y, tanhx(fmaf(c0, ca.z, ca.w)), ca.x), s0);
            s0 = fmaf(c1, fmaf(cb.y, tanhx(fmaf(c1, cb.z, cb.w)), cb.x), s0);
            s1 = fmaf(c2, fmaf(ca.y, tanhx(fmaf(c2, ca.z, ca.w)), ca.x), s1);
            s1 = fmaf(c3, fmaf(cb.y, tanhx(fmaf(c3, cb.z, cb.w)), cb.x), s1);
        }
        s0 += __shfl_xor_sync(0xFFFFFFFF, s0, 1);
        s0 += __shfl_xor_sync(0xFFFFFFFF, s0, 2);
        s1 += __shfl_xor_sync(0xFFFFFFFF, s1, 1);
        s1 += __shfl_xor_sync(0xFFFFFFFF, s1, 2);
        if (g == 0) {
            sc[r0] = score0 + s0;
            sc[r1] = score0 + s1;
        }
    }
    __syncthreads();

    // ===================== Final: out[b][e] = sum_t sc[t] * keys[b][t][e] ======
    // (UNMASKED scores, reproducing the reference bug faithfully.)
    // Rows 200..207: ksh is zero there, so their products contribute 0.
    if (tid < 192) {
        int e = tid % 12;
        int c = tid / 12;     // 16 chunks of 13 positions (16*13 = 208)
        float acc = 0.0f;
        int t0 = c * 13;
        #pragma unroll
        for (int t2 = t0; t2 < t0 + 13; ++t2)
            acc = fmaf(sc[t2], ksh[t2 * 12 + e], acc);
        psum[tid] = acc;
    }
    __syncthreads();
    if (tid < 12) {
        float acc = 0.0f;
        #pragma unroll
        for (int c = 0; c < 16; ++c) acc += psum[c * 12 + tid];
        out[b * 12 + tid] = acc;
    }
}

extern "C" void kernel_launch(void* const* d_in, const int* in_sizes, int n_in,
                              void* d_out, int out_size) {
    const float* query  = (const float*)d_in[0];
    const float* keys   = (const float*)d_in[1];
    // d_in[2] = mask (bool) -- intentionally unused: reference overwrites the
    // masked scores and matmuls the UNMASKED scores (bug reproduced faithfully)
    const float* W0     = (const float*)d_in[3];
    const float* b0     = (const float*)d_in[4];
    const float* W1     = (const float*)d_in[5];
    const float* b1     = (const float*)d_in[6];
    const float* alpha0 = (const float*)d_in[7];
    const float* alpha1 = (const float*)d_in[8];
    const float* mm0    = (const float*)d_in[9];
    const float* mv0    = (const float*)d_in[10];
    const float* mm1    = (const float*)d_in[11];
    const float* mv1    = (const float*)d_in[12];
    const float* ak     = (const float*)d_in[13];
    const float* ab     = (const float*)d_in[14];
    float* out = (float*)d_out;

    // idempotent attribute set, not a stream op -> graph-capture safe
    cudaFuncSetAttribute(din_kernel, cudaFuncAttributeMaxDynamicSharedMemorySize,
                         SMEM_BYTES);

    // batch-independent precompute (deterministic; same stream -> ordered)
    setup_kernel<<<1, 256>>>(W0, W1, b1, alpha0, alpha1, mm0, mv0, mm1, mv1, ak);

    int B = out_size / 12;  // [B, 1, 12]
    din_kernel<<<B, NT, SMEM_BYTES>>>(query, keys, b0, ab, out);
}

// round 14
// speedup vs baseline: 1.3522x; 1.3522x over previous
#include <cuda_runtime.h>

typedef unsigned int uint;

__device__ __forceinline__ float tanhx(float x) {
    float y; asm("tanh.approx.f32 %0, %1;" : "=f"(y) : "f"(x)); return y;
}
// pack two fp32 -> fp16x2 (RN); lo -> low half
__device__ __forceinline__ uint h2(float lo, float hi) {
    uint u; asm("cvt.rn.f16x2.f32 %0, %1, %2;" : "=r"(u) : "f"(hi), "f"(lo)); return u;
}
// Dice via tanh: dice(x) = x * fma(C2, tanh(fma(x, S2, MS2)), A2)
__device__ __forceinline__ float dice4(float x, float4 c) {
    return x * fmaf(c.y, tanhx(fmaf(x, c.z, c.w)), c.x);
}
// m16n8k16 fp16 warp MMA (A row-major, B col-major, fp32 accum)
__device__ __forceinline__ void mma_f16(float& d0, float& d1, float& d2, float& d3,
                                        uint a0, uint a1, uint a2, uint a3,
                                        uint b0, uint b1) {
    asm("mma.sync.aligned.m16n8k16.row.col.f32.f16.f16.f32 "
        "{%0,%1,%2,%3}, {%4,%5,%6,%7}, {%8,%9}, {%0,%1,%2,%3};"
        : "+f"(d0), "+f"(d1), "+f"(d2), "+f"(d3)
        : "r"(a0), "r"(a1), "r"(a2), "r"(a3), "r"(b0), "r"(b1));
}

static constexpr int NT = 416;   // 13 warps = 13 pos-tiles

// ---- batch-independent precomputed images (written by setup_kernel) ----
// g_W1h[kt5*160 + j5*32 + rw*4 + g] = { h2(W1[k0][j],W1[k0+1][j]),
//                                       h2(W1[k0+8][j],W1[k0+9][j]) }
//   with k0 = 16*kt5+2g, j = 8*j5+rw  (fp16 B-frags for layer-1)
__device__ uint2  g_W1h[800];
// g_WkH/g_WqH[o*4+g] = float4 of M components at k = {2g, 2g+1, 2g+8, 2g+9}
//   Wk = W0[12+k][o]-W0[24+k][o], Wq = W0[36+k][o]; k>=12 -> 0
__device__ float4 g_WkH[320];
__device__ float4 g_WqH[320];
__device__ float  g_Wbt[80 * 12];   // Wbt[o*12+i] = W0[i][o] + W0[24+i][o]
__device__ float4 g_cst[130];       // [0..79]=d0c, [80..119]=d1c, [120..129]=b1

__global__ void setup_kernel(
    const float* __restrict__ W0, const float* __restrict__ W1,
    const float* __restrict__ b1,
    const float* __restrict__ alpha0, const float* __restrict__ alpha1,
    const float* __restrict__ mm0, const float* __restrict__ mv0,
    const float* __restrict__ mm1, const float* __restrict__ mv1,
    const float* __restrict__ ak)
{
    const int tid = threadIdx.x;
    const float EPS = 1e-9f;
    // W1 fp16 B-fragment image
    for (int idx = tid; idx < 800; idx += 256) {
        int kt5 = idx / 160, r = idx % 160;
        int j5 = r / 32, rw = (r % 32) / 4, g = r % 4;
        int k0 = 16 * kt5 + 2 * g, j = 8 * j5 + rw;
        uint2 v;
        v.x = h2(W1[k0 * 40 + j],       W1[(k0 + 1) * 40 + j]);
        v.y = h2(W1[(k0 + 8) * 40 + j], W1[(k0 + 9) * 40 + j]);
        g_W1h[idx] = v;
    }
    // M component images (fp32; fused with q and packed to fp16 per batch)
    for (int idx = tid; idx < 320; idx += 256) {
        int o = idx / 4, g = idx % 4;
        int ks[4] = {2 * g, 2 * g + 1, 2 * g + 8, 2 * g + 9};
        float wk[4], wq[4];
        #pragma unroll
        for (int c = 0; c < 4; ++c) {
            int k = ks[c];
            if (k < 12) {
                wk[c] = W0[(12 + k) * 80 + o] - W0[(24 + k) * 80 + o];
                wq[c] = W0[(36 + k) * 80 + o];
            } else { wk[c] = 0.0f; wq[c] = 0.0f; }
        }
        g_WkH[idx] = make_float4(wk[0], wk[1], wk[2], wk[3]);
        g_WqH[idx] = make_float4(wq[0], wq[1], wq[2], wq[3]);
    }
    // Wbt transposed: Wbt[o*12+i] = W0[i][o] + W0[24+i][o]
    for (int idx = tid; idx < 960; idx += 256) {
        int o = idx / 12, i = idx % 12;
        g_Wbt[idx] = W0[i * 80 + o] + W0[(24 + i) * 80 + o];
    }
    // dice constants
    if (tid < 80) {
        float a  = alpha0[tid];
        float c2 = 0.5f * (1.0f - a);
        float s2 = 0.5f * rsqrtf(mv0[tid] + EPS);
        g_cst[tid] = make_float4(a + c2, c2, s2, -mm0[tid] * s2);
    }
    if (tid >= 128 && tid < 168) {
        int o = tid - 128;
        float a  = alpha1[o];
        float kk = ak[o];
        float c2 = 0.5f * (1.0f - a);
        float s2 = 0.5f * rsqrtf(mv1[o] + EPS);
        // h includes b1 (folded into hc accumulator init)
        g_cst[80 + o] = make_float4((a + c2) * kk, c2 * kk, s2, -mm1[o] * s2);
    }
    if (tid >= 192 && tid < 202) {
        int p = tid - 192;
        g_cst[120 + p] = make_float4(b1[4*p], b1[4*p+1], b1[4*p+2], b1[4*p+3]);
    }
}

// Shared layout (float slots):
static constexpr int O_KSH  = 0;                   // ksh [208][12] fp32   2496
static constexpr int O_W1H  = 2496;                // W1h 800 uint2        1600
static constexpr int O_MH   = O_W1H + 1600;        // Mh  320 uint2        640
static constexpr int O_CST  = O_MH + 640;          // d0c|d1c|b1d          520
static constexpr int O_BASE = O_CST + 520;         // base [80]            80
static constexpr int O_QH   = O_BASE + 80;         // qh float4[4]         16
static constexpr int O_SC   = O_QH + 16;           // sc [208]             208
static constexpr int O_PSUM = O_SC + 208;          // psum [192]           192
static constexpr int O_QS   = O_PSUM + 192;        // qs [12]              12
static constexpr int O_SC0  = O_QS + 12;           // score0 (+pad)        4
static constexpr int SMEM_FLOATS = O_SC0 + 4;      // 5768
static constexpr int SMEM_BYTES  = SMEM_FLOATS * 4;   // 23072 B -> 3 CTAs/SM

__global__ void __launch_bounds__(NT, 3) din_kernel(
    const float* __restrict__ query, const float* __restrict__ keys,
    const float* __restrict__ b0, const float* __restrict__ ab,
    float* __restrict__ out)
{
    extern __shared__ __align__(16) float smf[];
    float*  ksh   = smf + O_KSH;     // keys natural [208][12], rows 200-207 zero
    uint2*  W1h   = (uint2*)(smf + O_W1H);
    uint2*  Mh    = (uint2*)(smf + O_MH);
    float4* d0c   = (float4*)(smf + O_CST);
    float4* d1c   = (float4*)(smf + O_CST + 320);
    float*  b1d   = smf + O_CST + 480;
    float*  basef = smf + O_BASE;
    float4* qh    = (float4*)(smf + O_QH);
    float*  sc    = smf + O_SC;
    float*  psum  = smf + O_PSUM;
    float*  qs    = smf + O_QS;

    const int tid  = threadIdx.x;
    const int b    = blockIdx.x;
    const int wid  = tid >> 5;
    const int lane = tid & 31;
    const int g    = lane & 3;    // col group
    const int rw   = lane >> 2;   // row within fragment

    if (tid < 12) qs[tid] = query[b * 12 + tid];
    if (tid == 0) smf[O_SC0] = ab[0];
    __syncthreads();  // qs ready

    // ============ Phase A stage 1: copies + base + qh ============
    {
        const float4* gk = (const float4*)(keys + (size_t)b * 2400);
        float4* sk = (float4*)ksh;
        for (int i = tid; i < 600; i += NT) sk[i] = gk[i];
        if (tid < 96) ksh[2400 + tid] = 0.0f;
    }
    {   // W1h image copy (800 uint2 = 400 float4)
        const float4* src = (const float4*)g_W1h;
        float4* dst = (float4*)W1h;
        for (int i = tid; i < 400; i += NT) dst[i] = src[i];
    }
    if (tid < 130) ((float4*)(smf + O_CST))[tid] = g_cst[tid];
    if (tid < 4) {
        int gg = tid;
        qh[gg] = make_float4(qs[2 * gg], qs[2 * gg + 1],
                             (2 * gg + 8 < 12) ? qs[2 * gg + 8] : 0.0f,
                             (2 * gg + 9 < 12) ? qs[2 * gg + 9] : 0.0f);
    }
    if (tid < 80) {
        float s = b0[tid];
        const float4* wb = (const float4*)(g_Wbt + tid * 12);
        float4 w0v = wb[0], w1v = wb[1], w2v = wb[2];
        s += qs[0]*w0v.x + qs[1]*w0v.y + qs[2]*w0v.z  + qs[3]*w0v.w
           + qs[4]*w1v.x + qs[5]*w1v.y + qs[6]*w1v.z  + qs[7]*w1v.w
           + qs[8]*w2v.x + qs[9]*w2v.y + qs[10]*w2v.z + qs[11]*w2v.w;
        basef[tid] = s;
    }
    __syncthreads();

    // ============ Phase A stage 2: Mh = fp16(Wk + q*Wq); k=12 -> base ============
    for (int i = tid; i < 320; i += NT) {
        int g4 = i & 3;
        float4 wk = g_WkH[i];
        float4 wq = g_WqH[i];
        float4 q4 = qh[g4];
        float m0 = fmaf(q4.x, wq.x, wk.x);
        float m1 = fmaf(q4.y, wq.y, wk.y);
        float m2 = fmaf(q4.z, wq.z, wk.z);
        float m3 = fmaf(q4.w, wq.w, wk.w);
        if (g4 == 2) m2 = basef[i >> 2];   // k = 2g+8 = 12 -> bias row
        uint2 v;
        v.x = h2(m0, m1);
        v.y = h2(m2, m3);
        Mh[i] = v;
    }
    __syncthreads();

    // ===== Fused tile (1/warp): per kt5: 2x(layer0 MMA + dice) -> layer1 MMA =====
    {
        const float score0 = smf[O_SC0];
        const int pt = wid;                       // 13 warps, 13 tiles
        const int r0 = pt * 16 + rw, r1 = r0 + 8;

        // layer-0 A-frags (keys, fp16 RN). cols: {2g,2g+1} and {2g+8,2g+9};
        // col 12 = bias(1.0), cols 13-15 = 0.
        const float* k0p = ksh + r0 * 12;
        const float* k1p = ksh + r1 * 12;
        uint ka0 = h2(k0p[2 * g], k0p[2 * g + 1]);
        uint ka1 = h2(k1p[2 * g], k1p[2 * g + 1]);
        uint ka2, ka3;
        if (g < 2) {
            ka2 = h2(k0p[2 * g + 8], k0p[2 * g + 9]);
            ka3 = h2(k1p[2 * g + 8], k1p[2 * g + 9]);
        } else if (g == 2) {
            ka2 = 0x00003C00u;   // half2(1.0, 0.0): col12=1 (bias), col13=0
            ka3 = 0x00003C00u;
        } else {
            ka2 = 0u; ka3 = 0u;
        }

        // layer-1 accumulators, b1 folded into init
        float hc[5][4];
        #pragma unroll
        for (int j5 = 0; j5 < 5; ++j5) {
            float2 bb = *(const float2*)(b1d + j5 * 8 + 2 * g);
            hc[j5][0] = bb.x; hc[j5][1] = bb.y;
            hc[j5][2] = bb.x; hc[j5][3] = bb.y;
        }

        const uint2* wbase = W1h + rw * 4 + g;

        #pragma unroll
        for (int kt5 = 0; kt5 < 5; ++kt5) {
            uint a0, a1, a2, a3;
            {   // jt = 2*kt5: channels 16kt5 + {2g, 2g+1}
                int jt = 2 * kt5;
                float x0 = 0.f, x1 = 0.f, x2 = 0.f, x3 = 0.f;
                uint2 mb = Mh[(8 * jt + rw) * 4 + g];
                mma_f16(x0, x1, x2, x3, ka0, ka1, ka2, ka3, mb.x, mb.y);
                float4 ca = d0c[8 * jt + 2 * g];
                float4 cb = d0c[8 * jt + 2 * g + 1];
                a0 = h2(dice4(x0, ca), dice4(x1, cb));   // row rw
                a1 = h2(dice4(x2, ca), dice4(x3, cb));   // row rw+8
            }
            {   // jt = 2*kt5+1: channels 16kt5+8 + {2g, 2g+1}
                int jt = 2 * kt5 + 1;
                float x0 = 0.f, x1 = 0.f, x2 = 0.f, x3 = 0.f;
                uint2 mb = Mh[(8 * jt + rw) * 4 + g];
                mma_f16(x0, x1, x2, x3, ka0, ka1, ka2, ka3, mb.x, mb.y);
                float4 ca = d0c[8 * jt + 2 * g];
                float4 cb = d0c[8 * jt + 2 * g + 1];
                a2 = h2(dice4(x0, ca), dice4(x1, cb));
                a3 = h2(dice4(x2, ca), dice4(x3, cb));
            }
            // layer-1: 5 MMAs against k-tile kt5
            const uint2* wrow = wbase + kt5 * 160;
            #pragma unroll
            for (int j5 = 0; j5 < 5; ++j5) {
                uint2 bw = wrow[j5 * 32];
                mma_f16(hc[j5][0], hc[j5][1], hc[j5][2], hc[j5][3],
                        a0, a1, a2, a3, bw.x, bw.y);
            }
        }

        // ---- epilogue: dice1(+ak folded; h includes b1), row sums, reduce ----
        float s0 = 0.0f, s1 = 0.0f;
        #pragma unroll
        for (int j5 = 0; j5 < 5; ++j5) {
            const int ja = j5 * 8 + 2 * g;
            float4 ca = d1c[ja], cb = d1c[ja + 1];
            float c0 = hc[j5][0], c1 = hc[j5][1];
            float c2 = hc[j5][2], c3 = hc[j5][3];
            s0 = fmaf(c0, fmaf(ca.y, tanhx(fmaf(c0, ca.z, ca.w)), ca.x), s0);
            s0 = fmaf(c1, fmaf(cb.y, tanhx(fmaf(c1, cb.z, cb.w)), cb.x), s0);
            s1 = fmaf(c2, fmaf(ca.y, tanhx(fmaf(c2, ca.z, ca.w)), ca.x), s1);
            s1 = fmaf(c3, fmaf(cb.y, tanhx(fmaf(c3, cb.z, cb.w)), cb.x), s1);
        }
        s0 += __shfl_xor_sync(0xFFFFFFFF, s0, 1);
        s0 += __shfl_xor_sync(0xFFFFFFFF, s0, 2);
        s1 += __shfl_xor_sync(0xFFFFFFFF, s1, 1);
        s1 += __shfl_xor_sync(0xFFFFFFFF, s1, 2);
        if (g == 0) {
            sc[r0] = score0 + s0;
            sc[r1] = score0 + s1;
        }
    }
    __syncthreads();

    // ===================== Final: out[b][e] = sum_t sc[t] * keys[b][t][e] ======
    // (UNMASKED scores, reproducing the reference bug faithfully.)
    // Rows 200..207: ksh is zero there, so their products contribute 0.
    if (tid < 192) {
        int e = tid % 12;
        int c = tid / 12;     // 16 chunks of 13 positions (16*13 = 208)
        float acc = 0.0f;
        int t0 = c * 13;
        #pragma unroll
        for (int t2 = t0; t2 < t0 + 13; ++t2)
            acc = fmaf(sc[t2], ksh[t2 * 12 + e], acc);
        psum[tid] = acc;
    }
    __syncthreads();
    if (tid < 12) {
        float acc = 0.0f;
        #pragma unroll
        for (int c = 0; c < 16; ++c) acc += psum[c * 12 + tid];
        out[b * 12 + tid] = acc;
    }
}

extern "C" void kernel_launch(void* const* d_in, const int* in_sizes, int n_in,
                              void* d_out, int out_size) {
    const float* query  = (const float*)d_in[0];
    const float* keys   = (const float*)d_in[1];
    // d_in[2] = mask (bool) -- intentionally unused: reference overwrites the
    // masked scores and matmuls the UNMASKED scores (bug reproduced faithfully)
    const float* W0     = (const float*)d_in[3];
    const float* b0     = (const float*)d_in[4];
    const float* W1     = (const float*)d_in[5];
    const float* b1     = (const float*)d_in[6];
    const float* alpha0 = (const float*)d_in[7];
    const float* alpha1 = (const float*)d_in[8];
    const float* mm0    = (const float*)d_in[9];
    const float* mv0    = (const float*)d_in[10];
    const float* mm1    = (const float*)d_in[11];
    const float* mv1    = (const float*)d_in[12];
    const float* ak     = (const float*)d_in[13];
    const float* ab     = (const float*)d_in[14];
    float* out = (float*)d_out;

    // idempotent attribute set, not a stream op -> graph-capture safe
    cudaFuncSetAttribute(din_kernel, cudaFuncAttributeMaxDynamicSharedMemorySize,
                         SMEM_BYTES);

    // batch-independent precompute (deterministic; same stream -> ordered)
    setup_kernel<<<1, 256>>>(W0, W1, b1, alpha0, alpha1, mm0, mv0, mm1, mv1, ak);

    int B = out_size / 12;  // [B, 1, 12]
    din_kernel<<<B, NT, SMEM_BYTES>>>(query, keys, b0, ab, out);
}

// round 15
// speedup vs baseline: 1.3940x; 1.0309x over previous
#include <cuda_runtime.h>

typedef unsigned int uint;

__device__ __forceinline__ float tanhx(float x) {
    float y; asm("tanh.approx.f32 %0, %1;" : "=f"(y) : "f"(x)); return y;
}
// pack two fp32 -> fp16x2 (RN); lo -> low half
__device__ __forceinline__ uint h2(float lo, float hi) {
    uint u; asm("cvt.rn.f16x2.f32 %0, %1, %2;" : "=r"(u) : "f"(hi), "f"(lo)); return u;
}
// Dice via tanh: dice(x) = x * fma(C2, tanh(fma(x, S2, MS2)), A2)
__device__ __forceinline__ float dice4(float x, float4 c) {
    return x * fmaf(c.y, tanhx(fmaf(x, c.z, c.w)), c.x);
}
// m16n8k16 fp16 warp MMA (A row-major, B col-major, fp32 accum)
__device__ __forceinline__ void mma_f16(float& d0, float& d1, float& d2, float& d3,
                                        uint a0, uint a1, uint a2, uint a3,
                                        uint b0, uint b1) {
    asm("mma.sync.aligned.m16n8k16.row.col.f32.f16.f16.f32 "
        "{%0,%1,%2,%3}, {%4,%5,%6,%7}, {%8,%9}, {%0,%1,%2,%3};"
        : "+f"(d0), "+f"(d1), "+f"(d2), "+f"(d3)
        : "r"(a0), "r"(a1), "r"(a2), "r"(a3), "r"(b0), "r"(b1));
}

static constexpr int NT = 224;   // 7 warps x 2 pos-tiles = 14 tiles (13 real)

// ---- batch-independent precomputed images (written by setup_kernel) ----
// g_W1h[kt5*160 + j5*32 + rw*4 + g] = { h2(W1[k0][j],W1[k0+1][j]),
//                                       h2(W1[k0+8][j],W1[k0+9][j]) }
//   with k0 = 16*kt5+2g, j = 8*j5+rw  (fp16 B-frags for layer-1)
__device__ uint2  g_W1h[800];
// g_WkH/g_WqH[o*4+g] = float4 of M components at k = {2g, 2g+1, 2g+8, 2g+9}
//   Wk = W0[12+k][o]-W0[24+k][o], Wq = W0[36+k][o]; k>=12 -> 0
__device__ float4 g_WkH[320];
__device__ float4 g_WqH[320];
__device__ float  g_Wbt[80 * 12];   // Wbt[o*12+i] = W0[i][o] + W0[24+i][o]
__device__ float4 g_cst[130];       // [0..79]=d0c, [80..119]=d1c, [120..129]=b1

__global__ void setup_kernel(
    const float* __restrict__ W0, const float* __restrict__ W1,
    const float* __restrict__ b1,
    const float* __restrict__ alpha0, const float* __restrict__ alpha1,
    const float* __restrict__ mm0, const float* __restrict__ mv0,
    const float* __restrict__ mm1, const float* __restrict__ mv1,
    const float* __restrict__ ak)
{
    const int tid = threadIdx.x;
    const float EPS = 1e-9f;
    // W1 fp16 B-fragment image
    for (int idx = tid; idx < 800; idx += 256) {
        int kt5 = idx / 160, r = idx % 160;
        int j5 = r / 32, rw = (r % 32) / 4, g = r % 4;
        int k0 = 16 * kt5 + 2 * g, j = 8 * j5 + rw;
        uint2 v;
        v.x = h2(W1[k0 * 40 + j],       W1[(k0 + 1) * 40 + j]);
        v.y = h2(W1[(k0 + 8) * 40 + j], W1[(k0 + 9) * 40 + j]);
        g_W1h[idx] = v;
    }
    // M component images (fp32; fused with q and packed to fp16 per batch)
    for (int idx = tid; idx < 320; idx += 256) {
        int o = idx / 4, g = idx % 4;
        int ks[4] = {2 * g, 2 * g + 1, 2 * g + 8, 2 * g + 9};
        float wk[4], wq[4];
        #pragma unroll
        for (int c = 0; c < 4; ++c) {
            int k = ks[c];
            if (k < 12) {
                wk[c] = W0[(12 + k) * 80 + o] - W0[(24 + k) * 80 + o];
                wq[c] = W0[(36 + k) * 80 + o];
            } else { wk[c] = 0.0f; wq[c] = 0.0f; }
        }
        g_WkH[idx] = make_float4(wk[0], wk[1], wk[2], wk[3]);
        g_WqH[idx] = make_float4(wq[0], wq[1], wq[2], wq[3]);
    }
    // Wbt transposed: Wbt[o*12+i] = W0[i][o] + W0[24+i][o]
    for (int idx = tid; idx < 960; idx += 256) {
        int o = idx / 12, i = idx % 12;
        g_Wbt[idx] = W0[i * 80 + o] + W0[(24 + i) * 80 + o];
    }
    // dice constants
    if (tid < 80) {
        float a  = alpha0[tid];
        float c2 = 0.5f * (1.0f - a);
        float s2 = 0.5f * rsqrtf(mv0[tid] + EPS);
        g_cst[tid] = make_float4(a + c2, c2, s2, -mm0[tid] * s2);
    }
    if (tid >= 128 && tid < 168) {
        int o = tid - 128;
        float a  = alpha1[o];
        float kk = ak[o];
        float c2 = 0.5f * (1.0f - a);
        float s2 = 0.5f * rsqrtf(mv1[o] + EPS);
        // h includes b1 (folded into hc accumulator init)
        g_cst[80 + o] = make_float4((a + c2) * kk, c2 * kk, s2, -mm1[o] * s2);
    }
    if (tid >= 192 && tid < 202) {
        int p = tid - 192;
        g_cst[120 + p] = make_float4(b1[4*p], b1[4*p+1], b1[4*p+2], b1[4*p+3]);
    }
}

// Shared layout (float slots):
static constexpr int O_KSH  = 0;                   // ksh [224][12] fp32   2688
static constexpr int O_W1H  = 2688;                // W1h 800 uint2        1600
static constexpr int O_MH   = O_W1H + 1600;        // Mh  320 uint2        640
static constexpr int O_CST  = O_MH + 640;          // d0c|d1c|b1d          520
static constexpr int O_BASE = O_CST + 520;         // base [80]            80
static constexpr int O_QH   = O_BASE + 80;         // qh float4[4]         16
static constexpr int O_SC   = O_QH + 16;           // sc [224]             224
static constexpr int O_PSUM = O_SC + 224;          // psum [192]           192
static constexpr int O_QS   = O_PSUM + 192;        // qs [12]              12
static constexpr int O_SC0  = O_QS + 12;           // score0 (+pad)        4
static constexpr int SMEM_FLOATS = O_SC0 + 4;      // 5976
static constexpr int SMEM_BYTES  = SMEM_FLOATS * 4;   // 23904 B -> 3 CTAs/SM

__global__ void __launch_bounds__(NT, 3) din_kernel(
    const float* __restrict__ query, const float* __restrict__ keys,
    const float* __restrict__ b0, const float* __restrict__ ab,
    float* __restrict__ out)
{
    extern __shared__ __align__(16) float smf[];
    float*  ksh   = smf + O_KSH;     // keys natural [224][12], rows 200-223 zero
    uint2*  W1h   = (uint2*)(smf + O_W1H);
    uint2*  Mh    = (uint2*)(smf + O_MH);
    float4* d0c   = (float4*)(smf + O_CST);
    float4* d1c   = (float4*)(smf + O_CST + 320);
    float*  b1d   = smf + O_CST + 480;
    float*  basef = smf + O_BASE;
    float4* qh    = (float4*)(smf + O_QH);
    float*  sc    = smf + O_SC;
    float*  psum  = smf + O_PSUM;
    float*  qs    = smf + O_QS;

    const int tid  = threadIdx.x;
    const int b    = blockIdx.x;
    const int wid  = tid >> 5;
    const int lane = tid & 31;
    const int g    = lane & 3;    // col group
    const int rw   = lane >> 2;   // row within fragment

    if (tid < 12) qs[tid] = query[b * 12 + tid];
    if (tid == 0) smf[O_SC0] = ab[0];
    __syncthreads();  // qs ready

    // ============ Phase A stage 1: copies + base + qh ============
    {
        const float4* gk = (const float4*)(keys + (size_t)b * 2400);
        float4* sk = (float4*)ksh;
        for (int i = tid; i < 600; i += NT) sk[i] = gk[i];
        for (int i = tid; i < 288; i += NT) ksh[2400 + i] = 0.0f;
    }
    {   // W1h image copy (800 uint2 = 400 float4)
        const float4* src = (const float4*)g_W1h;
        float4* dst = (float4*)W1h;
        for (int i = tid; i < 400; i += NT) dst[i] = src[i];
    }
    if (tid < 130) ((float4*)(smf + O_CST))[tid] = g_cst[tid];
    if (tid < 4) {
        int gg = tid;
        qh[gg] = make_float4(qs[2 * gg], qs[2 * gg + 1],
                             (2 * gg + 8 < 12) ? qs[2 * gg + 8] : 0.0f,
                             (2 * gg + 9 < 12) ? qs[2 * gg + 9] : 0.0f);
    }
    if (tid < 80) {
        float s = b0[tid];
        const float4* wb = (const float4*)(g_Wbt + tid * 12);
        float4 w0v = wb[0], w1v = wb[1], w2v = wb[2];
        s += qs[0]*w0v.x + qs[1]*w0v.y + qs[2]*w0v.z  + qs[3]*w0v.w
           + qs[4]*w1v.x + qs[5]*w1v.y + qs[6]*w1v.z  + qs[7]*w1v.w
           + qs[8]*w2v.x + qs[9]*w2v.y + qs[10]*w2v.z + qs[11]*w2v.w;
        basef[tid] = s;
    }
    __syncthreads();

    // ============ Phase A stage 2: Mh = fp16(Wk + q*Wq); k=12 -> base ============
    for (int i = tid; i < 320; i += NT) {
        int g4 = i & 3;
        float4 wk = g_WkH[i];
        float4 wq = g_WqH[i];
        float4 q4 = qh[g4];
        float m0 = fmaf(q4.x, wq.x, wk.x);
        float m1 = fmaf(q4.y, wq.y, wk.y);
        float m2 = fmaf(q4.z, wq.z, wk.z);
        float m3 = fmaf(q4.w, wq.w, wk.w);
        if (g4 == 2) m2 = basef[i >> 2];   // k = 2g+8 = 12 -> bias row
        uint2 v;
        v.x = h2(m0, m1);
        v.y = h2(m2, m3);
        Mh[i] = v;
    }
    __syncthreads();

    // ===== Fused dual-tile warp loop: Mh/W1h/dice-const loads shared by 2 tiles =
    {
        const float score0 = smf[O_SC0];
        const int ptA = wid, ptB = wid + 7;       // 7 warps x 2 tiles
        const int r0a = ptA * 16 + rw, r1a = r0a + 8;
        const int r0b = ptB * 16 + rw, r1b = r0b + 8;

        // layer-0 A-frags for both tiles (keys fp16 RN).
        // cols {2g,2g+1} and {2g+8,2g+9}; col 12 = bias(1.0), 13-15 = 0.
        const float* p0a = ksh + r0a * 12;
        const float* p1a = ksh + r1a * 12;
        const float* p0b = ksh + r0b * 12;
        const float* p1b = ksh + r1b * 12;
        uint kaA0 = h2(p0a[2 * g], p0a[2 * g + 1]);
        uint kaA1 = h2(p1a[2 * g], p1a[2 * g + 1]);
        uint kaB0 = h2(p0b[2 * g], p0b[2 * g + 1]);
        uint kaB1 = h2(p1b[2 * g], p1b[2 * g + 1]);
        uint kaA2, kaA3, kaB2, kaB3;
        if (g < 2) {
            kaA2 = h2(p0a[2 * g + 8], p0a[2 * g + 9]);
            kaA3 = h2(p1a[2 * g + 8], p1a[2 * g + 9]);
            kaB2 = h2(p0b[2 * g + 8], p0b[2 * g + 9]);
            kaB3 = h2(p1b[2 * g + 8], p1b[2 * g + 9]);
        } else if (g == 2) {
            kaA2 = 0x00003C00u; kaA3 = 0x00003C00u;   // half2(1,0): bias col 12
            kaB2 = 0x00003C00u; kaB3 = 0x00003C00u;
        } else {
            kaA2 = 0u; kaA3 = 0u; kaB2 = 0u; kaB3 = 0u;
        }

        // layer-1 accumulators (b1 folded into init), both tiles
        float hcA[5][4], hcB[5][4];
        #pragma unroll
        for (int j5 = 0; j5 < 5; ++j5) {
            float2 bb = *(const float2*)(b1d + j5 * 8 + 2 * g);
            hcA[j5][0] = bb.x; hcA[j5][1] = bb.y;
            hcA[j5][2] = bb.x; hcA[j5][3] = bb.y;
            hcB[j5][0] = bb.x; hcB[j5][1] = bb.y;
            hcB[j5][2] = bb.x; hcB[j5][3] = bb.y;
        }

        const uint2* wbase = W1h + rw * 4 + g;

        #pragma unroll
        for (int kt5 = 0; kt5 < 5; ++kt5) {
            uint aA0, aA1, aA2, aA3, aB0, aB1, aB2, aB3;
            {   // jt = 2*kt5: channels 16kt5 + {2g, 2g+1}
                int jt = 2 * kt5;
                uint2 mb = Mh[(8 * jt + rw) * 4 + g];
                float4 ca = d0c[8 * jt + 2 * g];
                float4 cb = d0c[8 * jt + 2 * g + 1];
                float xa0=0.f, xa1=0.f, xa2=0.f, xa3=0.f;
                mma_f16(xa0, xa1, xa2, xa3, kaA0, kaA1, kaA2, kaA3, mb.x, mb.y);
                float xb0=0.f, xb1=0.f, xb2=0.f, xb3=0.f;
                mma_f16(xb0, xb1, xb2, xb3, kaB0, kaB1, kaB2, kaB3, mb.x, mb.y);
                aA0 = h2(dice4(xa0, ca), dice4(xa1, cb));
                aA1 = h2(dice4(xa2, ca), dice4(xa3, cb));
                aB0 = h2(dice4(xb0, ca), dice4(xb1, cb));
                aB1 = h2(dice4(xb2, ca), dice4(xb3, cb));
            }
            {   // jt = 2*kt5+1: channels 16kt5+8 + {2g, 2g+1}
                int jt = 2 * kt5 + 1;
                uint2 mb = Mh[(8 * jt + rw) * 4 + g];
                float4 ca = d0c[8 * jt + 2 * g];
                float4 cb = d0c[8 * jt + 2 * g + 1];
                float xa0=0.f, xa1=0.f, xa2=0.f, xa3=0.f;
                mma_f16(xa0, xa1, xa2, xa3, kaA0, kaA1, kaA2, kaA3, mb.x, mb.y);
                float xb0=0.f, xb1=0.f, xb2=0.f, xb3=0.f;
                mma_f16(xb0, xb1, xb2, xb3, kaB0, kaB1, kaB2, kaB3, mb.x, mb.y);
                aA2 = h2(dice4(xa0, ca), dice4(xa1, cb));
                aA3 = h2(dice4(xa2, ca), dice4(xa3, cb));
                aB2 = h2(dice4(xb0, ca), dice4(xb1, cb));
                aB3 = h2(dice4(xb2, ca), dice4(xb3, cb));
            }
            // layer-1: 5 B-frag loads serve BOTH tiles (10 MMAs)
            const uint2* wrow = wbase + kt5 * 160;
            #pragma unroll
            for (int j5 = 0; j5 < 5; ++j5) {
                uint2 bw = wrow[j5 * 32];
                mma_f16(hcA[j5][0], hcA[j5][1], hcA[j5][2], hcA[j5][3],
                        aA0, aA1, aA2, aA3, bw.x, bw.y);
                mma_f16(hcB[j5][0], hcB[j5][1], hcB[j5][2], hcB[j5][3],
                        aB0, aB1, aB2, aB3, bw.x, bw.y);
            }
        }

        // ---- epilogue: dice1(+ak folded; h includes b1), both tiles ----
        float sA0 = 0.f, sA1 = 0.f, sB0 = 0.f, sB1 = 0.f;
        #pragma unroll
        for (int j5 = 0; j5 < 5; ++j5) {
            const int ja = j5 * 8 + 2 * g;
            float4 ca = d1c[ja], cb = d1c[ja + 1];
            float a0 = hcA[j5][0], a1 = hcA[j5][1], a2 = hcA[j5][2], a3 = hcA[j5][3];
            float c0 = hcB[j5][0], c1 = hcB[j5][1], c2 = hcB[j5][2], c3 = hcB[j5][3];
            sA0 = fmaf(a0, fmaf(ca.y, tanhx(fmaf(a0, ca.z, ca.w)), ca.x), sA0);
            sA0 = fmaf(a1, fmaf(cb.y, tanhx(fmaf(a1, cb.z, cb.w)), cb.x), sA0);
            sA1 = fmaf(a2, fmaf(ca.y, tanhx(fmaf(a2, ca.z, ca.w)), ca.x), sA1);
            sA1 = fmaf(a3, fmaf(cb.y, tanhx(fmaf(a3, cb.z, cb.w)), cb.x), sA1);
            sB0 = fmaf(c0, fmaf(ca.y, tanhx(fmaf(c0, ca.z, ca.w)), ca.x), sB0);
            sB0 = fmaf(c1, fmaf(cb.y, tanhx(fmaf(c1, cb.z, cb.w)), cb.x), sB0);
            sB1 = fmaf(c2, fmaf(ca.y, tanhx(fmaf(c2, ca.z, ca.w)), ca.x), sB1);
            sB1 = fmaf(c3, fmaf(cb.y, tanhx(fmaf(c3, cb.z, cb.w)), cb.x), sB1);
        }
        sA0 += __shfl_xor_sync(0xFFFFFFFF, sA0, 1);
        sA0 += __shfl_xor_sync(0xFFFFFFFF, sA0, 2);
        sA1 += __shfl_xor_sync(0xFFFFFFFF, sA1, 1);
        sA1 += __shfl_xor_sync(0xFFFFFFFF, sA1, 2);
        sB0 += __shfl_xor_sync(0xFFFFFFFF, sB0, 1);
        sB0 += __shfl_xor_sync(0xFFFFFFFF, sB0, 2);
        sB1 += __shfl_xor_sync(0xFFFFFFFF, sB1, 1);
        sB1 += __shfl_xor_sync(0xFFFFFFFF, sB1, 2);
        if (g == 0) {
            sc[r0a] = score0 + sA0;
            sc[r1a] = score0 + sA1;
            sc[r0b] = score0 + sB0;   // rows >= 200 are dead (zero keys)
            sc[r1b] = score0 + sB1;
        }
    }
    __syncthreads();

    // ===================== Final: out[b][e] = sum_t sc[t] * keys[b][t][e] ======
    // (UNMASKED scores, reproducing the reference bug faithfully.)
    // Rows 200..207: ksh is zero there, so their products contribute 0.
    if (tid < 192) {
        int e = tid % 12;
        int c = tid / 12;     // 16 chunks of 13 positions (16*13 = 208)
        float acc = 0.0f;
        int t0 = c * 13;
        #pragma unroll
        for (int t2 = t0; t2 < t0 + 13; ++t2)
            acc = fmaf(sc[t2], ksh[t2 * 12 + e], acc);
        psum[tid] = acc;
    }
    __syncthreads();
    if (tid < 12) {
        float acc = 0.0f;
        #pragma unroll
        for (int c = 0; c < 16; ++c) acc += psum[c * 12 + tid];
        out[b * 12 + tid] = acc;
    }
}

extern "C" void kernel_launch(void* const* d_in, const int* in_sizes, int n_in,
                              void* d_out, int out_size) {
    const float* query  = (const float*)d_in[0];
    const float* keys   = (const float*)d_in[1];
    // d_in[2] = mask (bool) -- intentionally unused: reference overwrites the
    // masked scores and matmuls the UNMASKED scores (bug reproduced faithfully)
    const float* W0     = (const float*)d_in[3];
    const float* b0     = (const float*)d_in[4];
    const float* W1     = (const float*)d_in[5];
    const float* b1     = (const float*)d_in[6];
    const float* alpha0 = (const float*)d_in[7];
    const float* alpha1 = (const float*)d_in[8];
    const float* mm0    = (const float*)d_in[9];
    const float* mv0    = (const float*)d_in[10];
    const float* mm1    = (const float*)d_in[11];
    const float* mv1    = (const float*)d_in[12];
    const float* ak     = (const float*)d_in[13];
    const float* ab     = (const float*)d_in[14];
    float* out = (float*)d_out;

    // idempotent attribute set, not a stream op -> graph-capture safe
    cudaFuncSetAttribute(din_kernel, cudaFuncAttributeMaxDynamicSharedMemorySize,
                         SMEM_BYTES);

    // batch-independent precompute (deterministic; same stream -> ordered)
    setup_kernel<<<1, 256>>>(W0, W1, b1, alpha0, alpha1, mm0, mv0, mm1, mv1, ak);

    int B = out_size / 12;  // [B, 1, 12]
    din_kernel<<<B, NT, SMEM_BYTES>>>(query, keys, b0, ab, out);
}

// round 16
// speedup vs baseline: 1.5101x; 1.0832x over previous
#include <cuda_runtime.h>

typedef unsigned int uint;

__device__ __forceinline__ float tanhx(float x) {
    float y; asm("tanh.approx.f32 %0, %1;" : "=f"(y) : "f"(x)); return y;
}
// pack two fp32 -> fp16x2 (RN); lo -> low half
__device__ __forceinline__ uint h2(float lo, float hi) {
    uint u; asm("cvt.rn.f16x2.f32 %0, %1, %2;" : "=r"(u) : "f"(hi), "f"(lo)); return u;
}
// Dice via tanh: dice(x) = x * fma(C2, tanh(fma(x, S2, MS2)), A2)
__device__ __forceinline__ float dice4(float x, float4 c) {
    return x * fmaf(c.y, tanhx(fmaf(x, c.z, c.w)), c.x);
}
// m16n8k16 fp16 warp MMA (A row-major, B col-major, fp32 accum)
__device__ __forceinline__ void mma_f16(float& d0, float& d1, float& d2, float& d3,
                                        uint a0, uint a1, uint a2, uint a3,
                                        uint b0, uint b1) {
    asm("mma.sync.aligned.m16n8k16.row.col.f32.f16.f16.f32 "
        "{%0,%1,%2,%3}, {%4,%5,%6,%7}, {%8,%9}, {%0,%1,%2,%3};"
        : "+f"(d0), "+f"(d1), "+f"(d2), "+f"(d3)
        : "r"(a0), "r"(a1), "r"(a2), "r"(a3), "r"(b0), "r"(b1));
}

static constexpr int NT = 224;   // 7 warps x 2 pos-tiles = 14 tiles (13 real)

// ---- batch-independent precomputed images (written by setup_kernel) ----
// g_W1h[kt5*160 + j5*32 + rw*4 + g] = { h2(W1[k0][j],W1[k0+1][j]),
//                                       h2(W1[k0+8][j],W1[k0+9][j]) }
//   with k0 = 16*kt5+2g, j = 8*j5+rw  (fp16 B-frags for layer-1)
__device__ uint2  g_W1h[800];
// g_WkH/g_WqH[o*4+g] = float4 of M components at k = {2g, 2g+1, 2g+8, 2g+9}
//   Wk = W0[12+k][o]-W0[24+k][o], Wq = W0[36+k][o]; k>=12 -> 0
__device__ float4 g_WkH[320];
__device__ float4 g_WqH[320];
__device__ float  g_Wbt[80 * 12];   // Wbt[o*12+i] = W0[i][o] + W0[24+i][o]
__device__ float4 g_cst[130];       // [0..79]=d0c, [80..119]=d1c, [120..129]=b1

__global__ void setup_kernel(
    const float* __restrict__ W0, const float* __restrict__ W1,
    const float* __restrict__ b1,
    const float* __restrict__ alpha0, const float* __restrict__ alpha1,
    const float* __restrict__ mm0, const float* __restrict__ mv0,
    const float* __restrict__ mm1, const float* __restrict__ mv1,
    const float* __restrict__ ak)
{
    const int tid = threadIdx.x;
    const float EPS = 1e-9f;
    // W1 fp16 B-fragment image
    for (int idx = tid; idx < 800; idx += 256) {
        int kt5 = idx / 160, r = idx % 160;
        int j5 = r / 32, rw = (r % 32) / 4, g = r % 4;
        int k0 = 16 * kt5 + 2 * g, j = 8 * j5 + rw;
        uint2 v;
        v.x = h2(W1[k0 * 40 + j],       W1[(k0 + 1) * 40 + j]);
        v.y = h2(W1[(k0 + 8) * 40 + j], W1[(k0 + 9) * 40 + j]);
        g_W1h[idx] = v;
    }
    // M component images (fp32; fused with q and packed to fp16 per batch)
    for (int idx = tid; idx < 320; idx += 256) {
        int o = idx / 4, g = idx % 4;
        int ks[4] = {2 * g, 2 * g + 1, 2 * g + 8, 2 * g + 9};
        float wk[4], wq[4];
        #pragma unroll
        for (int c = 0; c < 4; ++c) {
            int k = ks[c];
            if (k < 12) {
                wk[c] = W0[(12 + k) * 80 + o] - W0[(24 + k) * 80 + o];
                wq[c] = W0[(36 + k) * 80 + o];
            } else { wk[c] = 0.0f; wq[c] = 0.0f; }
        }
        g_WkH[idx] = make_float4(wk[0], wk[1], wk[2], wk[3]);
        g_WqH[idx] = make_float4(wq[0], wq[1], wq[2], wq[3]);
    }
    // Wbt transposed: Wbt[o*12+i] = W0[i][o] + W0[24+i][o]
    for (int idx = tid; idx < 960; idx += 256) {
        int o = idx / 12, i = idx % 12;
        g_Wbt[idx] = W0[i * 80 + o] + W0[(24 + i) * 80 + o];
    }
    // dice constants
    if (tid < 80) {
        float a  = alpha0[tid];
        float c2 = 0.5f * (1.0f - a);
        float s2 = 0.5f * rsqrtf(mv0[tid] + EPS);
        g_cst[tid] = make_float4(a + c2, c2, s2, -mm0[tid] * s2);
    }
    if (tid >= 128 && tid < 168) {
        int o = tid - 128;
        float a  = alpha1[o];
        float kk = ak[o];
        float c2 = 0.5f * (1.0f - a);
        float s2 = 0.5f * rsqrtf(mv1[o] + EPS);
        // h includes b1 (folded into hc accumulator init)
        g_cst[80 + o] = make_float4((a + c2) * kk, c2 * kk, s2, -mm1[o] * s2);
    }
    if (tid >= 192 && tid < 202) {
        int p = tid - 192;
        g_cst[120 + p] = make_float4(b1[4*p], b1[4*p+1], b1[4*p+2], b1[4*p+3]);
    }
}

// Shared layout (float slots):
static constexpr int O_KSH  = 0;                   // ksh [224][12] fp32   2688
static constexpr int O_W1H  = 2688;                // W1h 800 uint2        1600
static constexpr int O_MH   = O_W1H + 1600;        // Mh  320 uint2        640
static constexpr int O_CST  = O_MH + 640;          // d0c|d1c|b1d          520
static constexpr int O_BASE = O_CST + 520;         // base [80]            80
static constexpr int O_QH   = O_BASE + 80;         // qh float4[4]         16
static constexpr int O_SC   = O_QH + 16;           // sc [224]             224
static constexpr int O_PSUM = O_SC + 224;          // psum [192]           192
static constexpr int O_QS   = O_PSUM + 192;        // qs [12]              12
static constexpr int O_SC0  = O_QS + 12;           // score0 (+pad)        4
static constexpr int SMEM_FLOATS = O_SC0 + 4;      // 5976
static constexpr int SMEM_BYTES  = SMEM_FLOATS * 4;   // 23904 B -> 4 CTAs/SM

__global__ void __launch_bounds__(NT, 4) din_kernel(
    const float* __restrict__ query, const float* __restrict__ keys,
    const float* __restrict__ b0, const float* __restrict__ ab,
    float* __restrict__ out)
{
    extern __shared__ __align__(16) float smf[];
    float*  ksh   = smf + O_KSH;     // keys natural [224][12], rows 200-223 zero
    uint2*  W1h   = (uint2*)(smf + O_W1H);
    uint2*  Mh    = (uint2*)(smf + O_MH);
    float4* d0c   = (float4*)(smf + O_CST);
    float4* d1c   = (float4*)(smf + O_CST + 320);
    float*  b1d   = smf + O_CST + 480;
    float*  basef = smf + O_BASE;
    float4* qh    = (float4*)(smf + O_QH);
    float*  sc    = smf + O_SC;
    float*  psum  = smf + O_PSUM;
    float*  qs    = smf + O_QS;

    const int tid  = threadIdx.x;
    const int b    = blockIdx.x;
    const int wid  = tid >> 5;
    const int lane = tid & 31;
    const int g    = lane & 3;    // col group
    const int rw   = lane >> 2;   // row within fragment

    if (tid < 12) qs[tid] = query[b * 12 + tid];
    if (tid == 0) smf[O_SC0] = ab[0];
    __syncthreads();  // qs ready

    // ============ Phase A stage 1: copies + base + qh ============
    {
        const float4* gk = (const float4*)(keys + (size_t)b * 2400);
        float4* sk = (float4*)ksh;
        for (int i = tid; i < 600; i += NT) sk[i] = gk[i];
        for (int i = tid; i < 288; i += NT) ksh[2400 + i] = 0.0f;
    }
    {   // W1h image copy (800 uint2 = 400 float4)
        const float4* src = (const float4*)g_W1h;
        float4* dst = (float4*)W1h;
        for (int i = tid; i < 400; i += NT) dst[i] = src[i];
    }
    if (tid < 130) ((float4*)(smf + O_CST))[tid] = g_cst[tid];
    if (tid < 4) {
        int gg = tid;
        qh[gg] = make_float4(qs[2 * gg], qs[2 * gg + 1],
                             (2 * gg + 8 < 12) ? qs[2 * gg + 8] : 0.0f,
                             (2 * gg + 9 < 12) ? qs[2 * gg + 9] : 0.0f);
    }
    if (tid < 80) {
        float s = b0[tid];
        const float4* wb = (const float4*)(g_Wbt + tid * 12);
        float4 w0v = wb[0], w1v = wb[1], w2v = wb[2];
        s += qs[0]*w0v.x + qs[1]*w0v.y + qs[2]*w0v.z  + qs[3]*w0v.w
           + qs[4]*w1v.x + qs[5]*w1v.y + qs[6]*w1v.z  + qs[7]*w1v.w
           + qs[8]*w2v.x + qs[9]*w2v.y + qs[10]*w2v.z + qs[11]*w2v.w;
        basef[tid] = s;
    }
    __syncthreads();

    // ============ Phase A stage 2: Mh = fp16(Wk + q*Wq); k=12 -> base ============
    for (int i = tid; i < 320; i += NT) {
        int g4 = i & 3;
        float4 wk = g_WkH[i];
        float4 wq = g_WqH[i];
        float4 q4 = qh[g4];
        float m0 = fmaf(q4.x, wq.x, wk.x);
        float m1 = fmaf(q4.y, wq.y, wk.y);
        float m2 = fmaf(q4.z, wq.z, wk.z);
        float m3 = fmaf(q4.w, wq.w, wk.w);
        if (g4 == 2) m2 = basef[i >> 2];   // k = 2g+8 = 12 -> bias row
        uint2 v;
        v.x = h2(m0, m1);
        v.y = h2(m2, m3);
        Mh[i] = v;
    }
    __syncthreads();

    // ===== Fused dual-tile warp loop: Mh/W1h/dice-const loads shared by 2 tiles =
    {
        const float score0 = smf[O_SC0];
        const int ptA = wid, ptB = wid + 7;       // 7 warps x 2 tiles
        const int r0a = ptA * 16 + rw, r1a = r0a + 8;
        const int r0b = ptB * 16 + rw, r1b = r0b + 8;

        // layer-0 A-frags for both tiles (keys fp16 RN).
        // cols {2g,2g+1} and {2g+8,2g+9}; col 12 = bias(1.0), 13-15 = 0.
        const float* p0a = ksh + r0a * 12;
        const float* p1a = ksh + r1a * 12;
        const float* p0b = ksh + r0b * 12;
        const float* p1b = ksh + r1b * 12;
        uint kaA0 = h2(p0a[2 * g], p0a[2 * g + 1]);
        uint kaA1 = h2(p1a[2 * g], p1a[2 * g + 1]);
        uint kaB0 = h2(p0b[2 * g], p0b[2 * g + 1]);
        uint kaB1 = h2(p1b[2 * g], p1b[2 * g + 1]);
        uint kaA2, kaA3, kaB2, kaB3;
        if (g < 2) {
            kaA2 = h2(p0a[2 * g + 8], p0a[2 * g + 9]);
            kaA3 = h2(p1a[2 * g + 8], p1a[2 * g + 9]);
            kaB2 = h2(p0b[2 * g + 8], p0b[2 * g + 9]);
            kaB3 = h2(p1b[2 * g + 8], p1b[2 * g + 9]);
        } else if (g == 2) {
            kaA2 = 0x00003C00u; kaA3 = 0x00003C00u;   // half2(1,0): bias col 12
            kaB2 = 0x00003C00u; kaB3 = 0x00003C00u;
        } else {
            kaA2 = 0u; kaA3 = 0u; kaB2 = 0u; kaB3 = 0u;
        }

        // layer-1 accumulators (b1 folded into init), both tiles
        float hcA[5][4], hcB[5][4];
        #pragma unroll
        for (int j5 = 0; j5 < 5; ++j5) {
            float2 bb = *(const float2*)(b1d + j5 * 8 + 2 * g);
            hcA[j5][0] = bb.x; hcA[j5][1] = bb.y;
            hcA[j5][2] = bb.x; hcA[j5][3] = bb.y;
            hcB[j5][0] = bb.x; hcB[j5][1] = bb.y;
            hcB[j5][2] = bb.x; hcB[j5][3] = bb.y;
        }

        const uint2* wbase = W1h + rw * 4 + g;

        #pragma unroll
        for (int kt5 = 0; kt5 < 5; ++kt5) {
            uint aA0, aA1, aA2, aA3, aB0, aB1, aB2, aB3;
            {   // jt = 2*kt5: channels 16kt5 + {2g, 2g+1}
                int jt = 2 * kt5;
                uint2 mb = Mh[(8 * jt + rw) * 4 + g];
                float4 ca = d0c[8 * jt + 2 * g];
                float4 cb = d0c[8 * jt + 2 * g + 1];
                float xa0=0.f, xa1=0.f, xa2=0.f, xa3=0.f;
                mma_f16(xa0, xa1, xa2, xa3, kaA0, kaA1, kaA2, kaA3, mb.x, mb.y);
                float xb0=0.f, xb1=0.f, xb2=0.f, xb3=0.f;
                mma_f16(xb0, xb1, xb2, xb3, kaB0, kaB1, kaB2, kaB3, mb.x, mb.y);
                aA0 = h2(dice4(xa0, ca), dice4(xa1, cb));
                aA1 = h2(dice4(xa2, ca), dice4(xa3, cb));
                aB0 = h2(dice4(xb0, ca), dice4(xb1, cb));
                aB1 = h2(dice4(xb2, ca), dice4(xb3, cb));
            }
            {   // jt = 2*kt5+1: channels 16kt5+8 + {2g, 2g+1}
                int jt = 2 * kt5 + 1;
                uint2 mb = Mh[(8 * jt + rw) * 4 + g];
                float4 ca = d0c[8 * jt + 2 * g];
                float4 cb = d0c[8 * jt + 2 * g + 1];
                float xa0=0.f, xa1=0.f, xa2=0.f, xa3=0.f;
                mma_f16(xa0, xa1, xa2, xa3, kaA0, kaA1, kaA2, kaA3, mb.x, mb.y);
                float xb0=0.f, xb1=0.f, xb2=0.f, xb3=0.f;
                mma_f16(xb0, xb1, xb2, xb3, kaB0, kaB1, kaB2, kaB3, mb.x, mb.y);
                aA2 = h2(dice4(xa0, ca), dice4(xa1, cb));
                aA3 = h2(dice4(xa2, ca), dice4(xa3, cb));
                aB2 = h2(dice4(xb0, ca), dice4(xb1, cb));
                aB3 = h2(dice4(xb2, ca), dice4(xb3, cb));
            }
            // layer-1: 5 B-frag loads serve BOTH tiles (10 MMAs)
            const uint2* wrow = wbase + kt5 * 160;
            #pragma unroll
            for (int j5 = 0; j5 < 5; ++j5) {
                uint2 bw = wrow[j5 * 32];
                mma_f16(hcA[j5][0], hcA[j5][1], hcA[j5][2], hcA[j5][3],
                        aA0, aA1, aA2, aA3, bw.x, bw.y);
                mma_f16(hcB[j5][0], hcB[j5][1], hcB[j5][2], hcB[j5][3],
                        aB0, aB1, aB2, aB3, bw.x, bw.y);
            }
        }

        // ---- epilogue: dice1(+ak folded; h includes b1), both tiles ----
        float sA0 = 0.f, sA1 = 0.f, sB0 = 0.f, sB1 = 0.f;
        #pragma unroll
        for (int j5 = 0; j5 < 5; ++j5) {
            const int ja = j5 * 8 + 2 * g;
            float4 ca = d1c[ja], cb = d1c[ja + 1];
            float a0 = hcA[j5][0], a1 = hcA[j5][1], a2 = hcA[j5][2], a3 = hcA[j5][3];
            float c0 = hcB[j5][0], c1 = hcB[j5][1], c2 = hcB[j5][2], c3 = hcB[j5][3];
            sA0 = fmaf(a0, fmaf(ca.y, tanhx(fmaf(a0, ca.z, ca.w)), ca.x), sA0);
            sA0 = fmaf(a1, fmaf(cb.y, tanhx(fmaf(a1, cb.z, cb.w)), cb.x), sA0);
            sA1 = fmaf(a2, fmaf(ca.y, tanhx(fmaf(a2, ca.z, ca.w)), ca.x), sA1);
            sA1 = fmaf(a3, fmaf(cb.y, tanhx(fmaf(a3, cb.z, cb.w)), cb.x), sA1);
            sB0 = fmaf(c0, fmaf(ca.y, tanhx(fmaf(c0, ca.z, ca.w)), ca.x), sB0);
            sB0 = fmaf(c1, fmaf(cb.y, tanhx(fmaf(c1, cb.z, cb.w)), cb.x), sB0);
            sB1 = fmaf(c2, fmaf(ca.y, tanhx(fmaf(c2, ca.z, ca.w)), ca.x), sB1);
            sB1 = fmaf(c3, fmaf(cb.y, tanhx(fmaf(c3, cb.z, cb.w)), cb.x), sB1);
        }
        sA0 += __shfl_xor_sync(0xFFFFFFFF, sA0, 1);
        sA0 += __shfl_xor_sync(0xFFFFFFFF, sA0, 2);
        sA1 += __shfl_xor_sync(0xFFFFFFFF, sA1, 1);
        sA1 += __shfl_xor_sync(0xFFFFFFFF, sA1, 2);
        sB0 += __shfl_xor_sync(0xFFFFFFFF, sB0, 1);
        sB0 += __shfl_xor_sync(0xFFFFFFFF, sB0, 2);
        sB1 += __shfl_xor_sync(0xFFFFFFFF, sB1, 1);
        sB1 += __shfl_xor_sync(0xFFFFFFFF, sB1, 2);
        if (g == 0) {
            sc[r0a] = score0 + sA0;
            sc[r1a] = score0 + sA1;
            sc[r0b] = score0 + sB0;   // rows >= 200 are dead (zero keys)
            sc[r1b] = score0 + sB1;
        }
    }
    __syncthreads();

    // ===================== Final: out[b][e] = sum_t sc[t] * keys[b][t][e] ======
    // (UNMASKED scores, reproducing the reference bug faithfully.)
    // Rows 200..207: ksh is zero there, so their products contribute 0.
    if (tid < 192) {
        int e = tid % 12;
        int c = tid / 12;     // 16 chunks of 13 positions (16*13 = 208)
        float acc = 0.0f;
        int t0 = c * 13;
        #pragma unroll
        for (int t2 = t0; t2 < t0 + 13; ++t2)
            acc = fmaf(sc[t2], ksh[t2 * 12 + e], acc);
        psum[tid] = acc;
    }
    __syncthreads();
    if (tid < 12) {
        float acc = 0.0f;
        #pragma unroll
        for (int c = 0; c < 16; ++c) acc += psum[c * 12 + tid];
        out[b * 12 + tid] = acc;
    }
}

extern "C" void kernel_launch(void* const* d_in, const int* in_sizes, int n_in,
                              void* d_out, int out_size) {
    const float* query  = (const float*)d_in[0];
    const float* keys   = (const float*)d_in[1];
    // d_in[2] = mask (bool) -- intentionally unused: reference overwrites the
    // masked scores and matmuls the UNMASKED scores (bug reproduced faithfully)
    const float* W0     = (const float*)d_in[3];
    const float* b0     = (const float*)d_in[4];
    const float* W1     = (const float*)d_in[5];
    const float* b1     = (const float*)d_in[6];
    const float* alpha0 = (const float*)d_in[7];
    const float* alpha1 = (const float*)d_in[8];
    const float* mm0    = (const float*)d_in[9];
    const float* mv0    = (const float*)d_in[10];
    const float* mm1    = (const float*)d_in[11];
    const float* mv1    = (const float*)d_in[12];
    const float* ak     = (const float*)d_in[13];
    const float* ab     = (const float*)d_in[14];
    float* out = (float*)d_out;

    // idempotent attribute set, not a stream op -> graph-capture safe
    cudaFuncSetAttribute(din_kernel, cudaFuncAttributeMaxDynamicSharedMemorySize,
                         SMEM_BYTES);

    // batch-independent precompute (deterministic; same stream -> ordered)
    setup_kernel<<<1, 256>>>(W0, W1, b1, alpha0, alpha1, mm0, mv0, mm1, mv1, ak);

    int B = out_size / 12;  // [B, 1, 12]
    din_kernel<<<B, NT, SMEM_BYTES>>>(query, keys, b0, ab, out);
}

// round 17
// speedup vs baseline: 1.6654x; 1.1029x over previous
#include <cuda_runtime.h>

typedef unsigned int uint;

__device__ __forceinline__ float tanhx(float x) {
    float y; asm("tanh.approx.f32 %0, %1;" : "=f"(y) : "f"(x)); return y;
}
// pack two fp32 -> fp16x2 (RN); lo -> low half
__device__ __forceinline__ uint h2(float lo, float hi) {
    uint u; asm("cvt.rn.f16x2.f32 %0, %1, %2;" : "=r"(u) : "f"(hi), "f"(lo)); return u;
}
// f16x2 primitives
__device__ __forceinline__ uint hfma2(uint a, uint b, uint c) {
    uint d; asm("fma.rn.f16x2 %0, %1, %2, %3;" : "=r"(d) : "r"(a), "r"(b), "r"(c));
    return d;
}
__device__ __forceinline__ uint hmul2(uint a, uint b) {
    uint d; asm("mul.rn.f16x2 %0, %1, %2;" : "=r"(d) : "r"(a), "r"(b));
    return d;
}
__device__ __forceinline__ uint htanh2(uint a) {
    uint d; asm("tanh.approx.f16x2 %0, %1;" : "=r"(d) : "r"(a));
    return d;
}
// packed Dice on a channel pair: x * fma(C2, tanh(fma(x,S2,MS2)), A2)
// dc = {A2, C2, S2, MS2} as f16x2 pairs
__device__ __forceinline__ uint dice2(uint x01, uint4 dc) {
    uint z = hfma2(x01, dc.z, dc.w);
    uint t = htanh2(z);
    uint w = hfma2(dc.y, t, dc.x);
    return hmul2(x01, w);
}
// scalar Dice (epilogue): dice(x) = x * fma(C2, tanh(fma(x, S2, MS2)), A2)
__device__ __forceinline__ float dice4(float x, float4 c) {
    return x * fmaf(c.y, tanhx(fmaf(x, c.z, c.w)), c.x);
}
// m16n8k16 fp16 warp MMA (A row-major, B col-major, fp32 accum)
__device__ __forceinline__ void mma_f16(float& d0, float& d1, float& d2, float& d3,
                                        uint a0, uint a1, uint a2, uint a3,
                                        uint b0, uint b1) {
    asm("mma.sync.aligned.m16n8k16.row.col.f32.f16.f16.f32 "
        "{%0,%1,%2,%3}, {%4,%5,%6,%7}, {%8,%9}, {%0,%1,%2,%3};"
        : "+f"(d0), "+f"(d1), "+f"(d2), "+f"(d3)
        : "r"(a0), "r"(a1), "r"(a2), "r"(a3), "r"(b0), "r"(b1));
}

static constexpr int NT = 224;   // 7 warps x 2 pos-tiles = 14 tiles (13 real)

// ---- batch-independent precomputed images (written by setup_kernel) ----
// g_W1h[kt5*160 + j5*32 + rw*4 + g] = { h2(W1[k0][j],W1[k0+1][j]),
//                                       h2(W1[k0+8][j],W1[k0+9][j]) }
//   with k0 = 16*kt5+2g, j = 8*j5+rw  (fp16 B-frags for layer-1)
__device__ uint2  g_W1h[800];
// g_WkH/g_WqH[o*4+g] = float4 of M components at k = {2g, 2g+1, 2g+8, 2g+9}
__device__ float4 g_WkH[320];
__device__ float4 g_WqH[320];
__device__ float  g_Wbt[80 * 12];   // Wbt[o*12+i] = W0[i][o] + W0[24+i][o]
// g_cst: [0..39] d0h (uint4 half2 dice0 consts per channel-pair),
//        [40..79] d1c (float4), [80..89] b1 (float4 x10)
__device__ float4 g_cst[90];

__global__ void setup_kernel(
    const float* __restrict__ W0, const float* __restrict__ W1,
    const float* __restrict__ b1,
    const float* __restrict__ alpha0, const float* __restrict__ alpha1,
    const float* __restrict__ mm0, const float* __restrict__ mv0,
    const float* __restrict__ mm1, const float* __restrict__ mv1,
    const float* __restrict__ ak)
{
    const int tid = threadIdx.x;
    const float EPS = 1e-9f;
    // W1 fp16 B-fragment image
    for (int idx = tid; idx < 800; idx += 256) {
        int kt5 = idx / 160, r = idx % 160;
        int j5 = r / 32, rw = (r % 32) / 4, g = r % 4;
        int k0 = 16 * kt5 + 2 * g, j = 8 * j5 + rw;
        uint2 v;
        v.x = h2(W1[k0 * 40 + j],       W1[(k0 + 1) * 40 + j]);
        v.y = h2(W1[(k0 + 8) * 40 + j], W1[(k0 + 9) * 40 + j]);
        g_W1h[idx] = v;
    }
    // M component images (fp32; fused with q and packed to fp16 per batch)
    for (int idx = tid; idx < 320; idx += 256) {
        int o = idx / 4, g = idx % 4;
        int ks[4] = {2 * g, 2 * g + 1, 2 * g + 8, 2 * g + 9};
        float wk[4], wq[4];
        #pragma unroll
        for (int c = 0; c < 4; ++c) {
            int k = ks[c];
            if (k < 12) {
                wk[c] = W0[(12 + k) * 80 + o] - W0[(24 + k) * 80 + o];
                wq[c] = W0[(36 + k) * 80 + o];
            } else { wk[c] = 0.0f; wq[c] = 0.0f; }
        }
        g_WkH[idx] = make_float4(wk[0], wk[1], wk[2], wk[3]);
        g_WqH[idx] = make_float4(wq[0], wq[1], wq[2], wq[3]);
    }
    // Wbt transposed: Wbt[o*12+i] = W0[i][o] + W0[24+i][o]
    for (int idx = tid; idx < 960; idx += 256) {
        int o = idx / 12, i = idx % 12;
        g_Wbt[idx] = W0[i * 80 + o] + W0[(24 + i) * 80 + o];
    }
    // dice0 constants, packed f16x2 per channel pair p = (2p, 2p+1)
    if (tid < 40) {
        int p = tid;
        float a0v = alpha0[2 * p],     a1v = alpha0[2 * p + 1];
        float c20 = 0.5f * (1.0f - a0v), c21 = 0.5f * (1.0f - a1v);
        float s20 = 0.5f * rsqrtf(mv0[2 * p] + EPS);
        float s21 = 0.5f * rsqrtf(mv0[2 * p + 1] + EPS);
        uint4 v;
        v.x = h2(a0v + c20, a1v + c21);            // A2
        v.y = h2(c20, c21);                        // C2
        v.z = h2(s20, s21);                        // S2
        v.w = h2(-mm0[2 * p] * s20, -mm0[2 * p + 1] * s21);  // MS2
        float4 f; f.x = __uint_as_float(v.x); f.y = __uint_as_float(v.y);
        f.z = __uint_as_float(v.z); f.w = __uint_as_float(v.w);
        g_cst[p] = f;
    }
    // dice1 constants (f32, ak folded; h includes b1 via accumulator init)
    if (tid >= 128 && tid < 168) {
        int o = tid - 128;
        float a  = alpha1[o];
        float kk = ak[o];
        float c2 = 0.5f * (1.0f - a);
        float s2 = 0.5f * rsqrtf(mv1[o] + EPS);
        g_cst[40 + o] = make_float4((a + c2) * kk, c2 * kk, s2, -mm1[o] * s2);
    }
    if (tid >= 192 && tid < 202) {
        int p = tid - 192;
        g_cst[80 + p] = make_float4(b1[4*p], b1[4*p+1], b1[4*p+2], b1[4*p+3]);
    }
}

// Shared layout (float slots):
static constexpr int O_KSH  = 0;                   // ksh [224][12] fp32   2688
static constexpr int O_W1H  = 2688;                // W1h 800 uint2        1600
static constexpr int O_MH   = O_W1H + 1600;        // Mh  320 uint2        640
static constexpr int O_CST  = O_MH + 640;          // d0h|d1c|b1d          360
static constexpr int O_BASE = O_CST + 360;         // base [80]            80
static constexpr int O_QH   = O_BASE + 80;         // qh float4[4]         16
static constexpr int O_SC   = O_QH + 16;           // sc [224]             224
static constexpr int O_PSUM = O_SC + 224;          // psum [192]           192
static constexpr int O_QS   = O_PSUM + 192;        // qs [12]              12
static constexpr int O_SC0  = O_QS + 12;           // score0 (+pad)        4
static constexpr int SMEM_FLOATS = O_SC0 + 4;      // 5816
static constexpr int SMEM_BYTES  = SMEM_FLOATS * 4;   // 23264 B -> 4 CTAs/SM

__global__ void __launch_bounds__(NT, 4) din_kernel(
    const float* __restrict__ query, const float* __restrict__ keys,
    const float* __restrict__ b0, const float* __restrict__ ab,
    float* __restrict__ out)
{
    extern __shared__ __align__(16) float smf[];
    float*  ksh   = smf + O_KSH;     // keys natural [224][12], rows 200-223 zero
    uint2*  W1h   = (uint2*)(smf + O_W1H);
    uint2*  Mh    = (uint2*)(smf + O_MH);
    uint4*  d0h   = (uint4*)(smf + O_CST);          // 40 entries
    float4* d1c   = (float4*)(smf + O_CST + 160);   // 40 entries
    float*  b1d   = smf + O_CST + 320;              // 40 floats
    float*  basef = smf + O_BASE;
    float4* qh    = (float4*)(smf + O_QH);
    float*  sc    = smf + O_SC;
    float*  psum  = smf + O_PSUM;
    float*  qs    = smf + O_QS;

    const int tid  = threadIdx.x;
    const int b    = blockIdx.x;
    const int wid  = tid >> 5;
    const int lane = tid & 31;
    const int g    = lane & 3;    // col group
    const int rw   = lane >> 2;   // row within fragment

    if (tid < 12) qs[tid] = query[b * 12 + tid];
    if (tid == 0) smf[O_SC0] = ab[0];
    __syncthreads();  // qs ready

    // ============ Phase A stage 1: copies + base + qh ============
    {
        const float4* gk = (const float4*)(keys + (size_t)b * 2400);
        float4* sk = (float4*)ksh;
        for (int i = tid; i < 600; i += NT) sk[i] = gk[i];
        for (int i = tid; i < 288; i += NT) ksh[2400 + i] = 0.0f;
    }
    {   // W1h image copy (800 uint2 = 400 float4)
        const float4* src = (const float4*)g_W1h;
        float4* dst = (float4*)W1h;
        for (int i = tid; i < 400; i += NT) dst[i] = src[i];
    }
    if (tid < 90) ((float4*)(smf + O_CST))[tid] = g_cst[tid];
    if (tid < 4) {
        int gg = tid;
        qh[gg] = make_float4(qs[2 * gg], qs[2 * gg + 1],
                             (2 * gg + 8 < 12) ? qs[2 * gg + 8] : 0.0f,
                             (2 * gg + 9 < 12) ? qs[2 * gg + 9] : 0.0f);
    }
    if (tid < 80) {
        float s = b0[tid];
        const float4* wb = (const float4*)(g_Wbt + tid * 12);
        float4 w0v = wb[0], w1v = wb[1], w2v = wb[2];
        s += qs[0]*w0v.x + qs[1]*w0v.y + qs[2]*w0v.z  + qs[3]*w0v.w
           + qs[4]*w1v.x + qs[5]*w1v.y + qs[6]*w1v.z  + qs[7]*w1v.w
           + qs[8]*w2v.x + qs[9]*w2v.y + qs[10]*w2v.z + qs[11]*w2v.w;
        basef[tid] = s;
    }
    __syncthreads();

    // ============ Phase A stage 2: Mh = fp16(Wk + q*Wq); k=12 -> base ============
    for (int i = tid; i < 320; i += NT) {
        int g4 = i & 3;
        float4 wk = g_WkH[i];
        float4 wq = g_WqH[i];
        float4 q4 = qh[g4];
        float m0 = fmaf(q4.x, wq.x, wk.x);
        float m1 = fmaf(q4.y, wq.y, wk.y);
        float m2 = fmaf(q4.z, wq.z, wk.z);
        float m3 = fmaf(q4.w, wq.w, wk.w);
        if (g4 == 2) m2 = basef[i >> 2];   // k = 2g+8 = 12 -> bias row
        uint2 v;
        v.x = h2(m0, m1);
        v.y = h2(m2, m3);
        Mh[i] = v;
    }
    __syncthreads();

    // ===== Fused dual-tile warp loop: Mh/W1h/dice-const loads shared by 2 tiles =
    {
        const float score0 = smf[O_SC0];
        const int ptA = wid, ptB = wid + 7;       // 7 warps x 2 tiles
        const int r0a = ptA * 16 + rw, r1a = r0a + 8;
        const int r0b = ptB * 16 + rw, r1b = r0b + 8;

        // layer-0 A-frags for both tiles (keys fp16 RN).
        // cols {2g,2g+1} and {2g+8,2g+9}; col 12 = bias(1.0), 13-15 = 0.
        const float* p0a = ksh + r0a * 12;
        const float* p1a = ksh + r1a * 12;
        const float* p0b = ksh + r0b * 12;
        const float* p1b = ksh + r1b * 12;
        uint kaA0 = h2(p0a[2 * g], p0a[2 * g + 1]);
        uint kaA1 = h2(p1a[2 * g], p1a[2 * g + 1]);
        uint kaB0 = h2(p0b[2 * g], p0b[2 * g + 1]);
        uint kaB1 = h2(p1b[2 * g], p1b[2 * g + 1]);
        uint kaA2, kaA3, kaB2, kaB3;
        if (g < 2) {
            kaA2 = h2(p0a[2 * g + 8], p0a[2 * g + 9]);
            kaA3 = h2(p1a[2 * g + 8], p1a[2 * g + 9]);
            kaB2 = h2(p0b[2 * g + 8], p0b[2 * g + 9]);
            kaB3 = h2(p1b[2 * g + 8], p1b[2 * g + 9]);
        } else if (g == 2) {
            kaA2 = 0x00003C00u; kaA3 = 0x00003C00u;   // half2(1,0): bias col 12
            kaB2 = 0x00003C00u; kaB3 = 0x00003C00u;
        } else {
            kaA2 = 0u; kaA3 = 0u; kaB2 = 0u; kaB3 = 0u;
        }

        // layer-1 accumulators (b1 folded into init), both tiles
        float hcA[5][4], hcB[5][4];
        #pragma unroll
        for (int j5 = 0; j5 < 5; ++j5) {
            float2 bb = *(const float2*)(b1d + j5 * 8 + 2 * g);
            hcA[j5][0] = bb.x; hcA[j5][1] = bb.y;
            hcA[j5][2] = bb.x; hcA[j5][3] = bb.y;
            hcB[j5][0] = bb.x; hcB[j5][1] = bb.y;
            hcB[j5][2] = bb.x; hcB[j5][3] = bb.y;
        }

        const uint2* wbase = W1h + rw * 4 + g;

        #pragma unroll
        for (int kt5 = 0; kt5 < 5; ++kt5) {
            uint aA0, aA1, aA2, aA3, aB0, aB1, aB2, aB3;
            {   // jt = 2*kt5: channel pair 4*jt+g = (8jt+2g, 8jt+2g+1)
                int jt = 2 * kt5;
                uint2 mb = Mh[(8 * jt + rw) * 4 + g];
                uint4 dc = d0h[4 * jt + g];
                float xa0=0.f, xa1=0.f, xa2=0.f, xa3=0.f;
                mma_f16(xa0, xa1, xa2, xa3, kaA0, kaA1, kaA2, kaA3, mb.x, mb.y);
                float xb0=0.f, xb1=0.f, xb2=0.f, xb3=0.f;
                mma_f16(xb0, xb1, xb2, xb3, kaB0, kaB1, kaB2, kaB3, mb.x, mb.y);
                aA0 = dice2(h2(xa0, xa1), dc);
                aA1 = dice2(h2(xa2, xa3), dc);
                aB0 = dice2(h2(xb0, xb1), dc);
                aB1 = dice2(h2(xb2, xb3), dc);
            }
            {   // jt = 2*kt5+1
                int jt = 2 * kt5 + 1;
                uint2 mb = Mh[(8 * jt + rw) * 4 + g];
                uint4 dc = d0h[4 * jt + g];
                float xa0=0.f, xa1=0.f, xa2=0.f, xa3=0.f;
                mma_f16(xa0, xa1, xa2, xa3, kaA0, kaA1, kaA2, kaA3, mb.x, mb.y);
                float xb0=0.f, xb1=0.f, xb2=0.f, xb3=0.f;
                mma_f16(xb0, xb1, xb2, xb3, kaB0, kaB1, kaB2, kaB3, mb.x, mb.y);
                aA2 = dice2(h2(xa0, xa1), dc);
                aA3 = dice2(h2(xa2, xa3), dc);
                aB2 = dice2(h2(xb0, xb1), dc);
                aB3 = dice2(h2(xb2, xb3), dc);
            }
            // layer-1: 5 B-frag loads serve BOTH tiles (10 MMAs)
            const uint2* wrow = wbase + kt5 * 160;
            #pragma unroll
            for (int j5 = 0; j5 < 5; ++j5) {
                uint2 bw = wrow[j5 * 32];
                mma_f16(hcA[j5][0], hcA[j5][1], hcA[j5][2], hcA[j5][3],
                        aA0, aA1, aA2, aA3, bw.x, bw.y);
                mma_f16(hcB[j5][0], hcB[j5][1], hcB[j5][2], hcB[j5][3],
                        aB0, aB1, aB2, aB3, bw.x, bw.y);
            }
        }

        // ---- epilogue: dice1 f32 (+ak folded; h includes b1), both tiles ----
        float sA0 = 0.f, sA1 = 0.f, sB0 = 0.f, sB1 = 0.f;
        #pragma unroll
        for (int j5 = 0; j5 < 5; ++j5) {
            const int ja = j5 * 8 + 2 * g;
            float4 ca = d1c[ja], cb = d1c[ja + 1];
            float a0 = hcA[j5][0], a1 = hcA[j5][1], a2 = hcA[j5][2], a3 = hcA[j5][3];
            float c0 = hcB[j5][0], c1 = hcB[j5][1], c2 = hcB[j5][2], c3 = hcB[j5][3];
            sA0 = fmaf(a0, fmaf(ca.y, tanhx(fmaf(a0, ca.z, ca.w)), ca.x), sA0);
            sA0 = fmaf(a1, fmaf(cb.y, tanhx(fmaf(a1, cb.z, cb.w)), cb.x), sA0);
            sA1 = fmaf(a2, fmaf(ca.y, tanhx(fmaf(a2, ca.z, ca.w)), ca.x), sA1);
            sA1 = fmaf(a3, fmaf(cb.y, tanhx(fmaf(a3, cb.z, cb.w)), cb.x), sA1);
            sB0 = fmaf(c0, fmaf(ca.y, tanhx(fmaf(c0, ca.z, ca.w)), ca.x), sB0);
            sB0 = fmaf(c1, fmaf(cb.y, tanhx(fmaf(c1, cb.z, cb.w)), cb.x), sB0);
            sB1 = fmaf(c2, fmaf(ca.y, tanhx(fmaf(c2, ca.z, ca.w)), ca.x), sB1);
            sB1 = fmaf(c3, fmaf(cb.y, tanhx(fmaf(c3, cb.z, cb.w)), cb.x), sB1);
        }
        sA0 += __shfl_xor_sync(0xFFFFFFFF, sA0, 1);
        sA0 += __shfl_xor_sync(0xFFFFFFFF, sA0, 2);
        sA1 += __shfl_xor_sync(0xFFFFFFFF, sA1, 1);
        sA1 += __shfl_xor_sync(0xFFFFFFFF, sA1, 2);
        sB0 += __shfl_xor_sync(0xFFFFFFFF, sB0, 1);
        sB0 += __shfl_xor_sync(0xFFFFFFFF, sB0, 2);
        sB1 += __shfl_xor_sync(0xFFFFFFFF, sB1, 1);
        sB1 += __shfl_xor_sync(0xFFFFFFFF, sB1, 2);
        if (g == 0) {
            sc[r0a] = score0 + sA0;
            sc[r1a] = score0 + sA1;
            sc[r0b] = score0 + sB0;   // rows >= 200 are dead (zero keys)
            sc[r1b] = score0 + sB1;
        }
    }
    __syncthreads();

    // ===================== Final: out[b][e] = sum_t sc[t] * keys[b][t][e] ======
    // (UNMASKED scores, reproducing the reference bug faithfully.)
    // Rows 200..207: ksh is zero there, so their products contribute 0.
    if (tid < 192) {
        int e = tid % 12;
        int c = tid / 12;     // 16 chunks of 13 positions (16*13 = 208)
        float acc = 0.0f;
        int t0 = c * 13;
        #pragma unroll
        for (int t2 = t0; t2 < t0 + 13; ++t2)
            acc = fmaf(sc[t2], ksh[t2 * 12 + e], acc);
        psum[tid] = acc;
    }
    __syncthreads();
    if (tid < 12) {
        float acc = 0.0f;
        #pragma unroll
        for (int c = 0; c < 16; ++c) acc += psum[c * 12 + tid];
        out[b * 12 + tid] = acc;
    }
}

extern "C" void kernel_launch(void* const* d_in, const int* in_sizes, int n_in,
                              void* d_out, int out_size) {
    const float* query  = (const float*)d_in[0];
    const float* keys   = (const float*)d_in[1];
    // d_in[2] = mask (bool) -- intentionally unused: reference overwrites the
    // masked scores and matmuls the UNMASKED scores (bug reproduced faithfully)
    const float* W0     = (const float*)d_in[3];
    const float* b0     = (const float*)d_in[4];
    const float* W1     = (const float*)d_in[5];
    const float* b1     = (const float*)d_in[6];
    const float* alpha0 = (const float*)d_in[7];
    const float* alpha1 = (const float*)d_in[8];
    const float* mm0    = (const float*)d_in[9];
    const float* mv0    = (const float*)d_in[10];
    const float* mm1    = (const float*)d_in[11];
    const float* mv1    = (const float*)d_in[12];
    const float* ak     = (const float*)d_in[13];
    const float* ab     = (const float*)d_in[14];
    float* out = (float*)d_out;

    // idempotent attribute set, not a stream op -> graph-capture safe
    cudaFuncSetAttribute(din_kernel, cudaFuncAttributeMaxDynamicSharedMemorySize,
                         SMEM_BYTES);

    // batch-independent precompute (deterministic; same stream -> ordered)
    setup_kernel<<<1, 256>>>(W0, W1, b1, alpha0, alpha1, mm0, mv0, mm1, mv1, ak);

    int B = out_size / 12;  // [B, 1, 12]
    din_kernel<<<B, NT, SMEM_BYTES>>>(query, keys, b0, ab, out);
}